// round 15
// baseline (speedup 1.0000x reference)
#include <cuda_runtime.h>
#include <cuda_fp16.h>
#include <cstdint>

#define NN    50000
#define EE    800000
#define ETOT  (EE + NN)
#define FIN   128
#define H1DIM 128   // HEADS*HID
#define NHEAD 8
#define CLS   40
#define NEG   0.2f
#define G1M   128   // rows per gemm block
#define WPAD  68    // smem word stride (68 mod 32 == 4 -> conflict-free frags)

// ---------------- device scratch (static, allocation-free) ----------------
__device__ __half   g_h1h[(size_t)NN * H1DIM];    // layer-1 messages, fp16
__device__ __half   g_hacth[(size_t)NN * H1DIM];  // ELU output, fp16
__device__ __half   g_h2h[(size_t)NN * CLS];      // layer-2 messages, fp16
__device__ float    g_e1s[NN * NHEAD];
__device__ float    g_e1d[NN * NHEAD];
__device__ float    g_e2s[NN];
__device__ float    g_e2d[NN];
__device__ int      g_rowptr[NN + 1];
__device__ int      g_counts[NN];
__device__ int      g_fill[NN];
__device__ int      g_srcs[ETOT];
__device__ uint32_t g_w1h[H1DIM * 64];   // W1 half2-packed, n-major: [n*64 + k/2]
__device__ uint32_t g_w2h[CLS * 64];     // W2 half2-packed, n-major
__device__ int      g_is64;

// ---------------- fast exp: pure FFMA/ALU, no MUFU ----------------
__device__ __forceinline__ float fexp(float x) {
    float t = x * 1.442695041f;
    t = fminf(fmaxf(t, -125.f), 125.f);
    float biased = t + 12582912.f;
    int   ni = __float_as_int(biased) - 0x4B400000;
    float n  = biased - 12582912.f;
    float f  = fmaf(-n, 0.69314718056f, x);
    float p  = fmaf(f, 8.3333333e-3f, 4.1666667e-2f);
    p = fmaf(p, f, 0.16666667f);
    p = fmaf(p, f, 0.5f);
    p = fmaf(p, f, 1.0f);
    p = fmaf(p, f, 1.0f);
    return p * __int_as_float((ni + 127) << 23);
}

__device__ __forceinline__ uint32_t pack_h2(float a, float b) {
    __half2 h = __floats2half2_rn(a, b);
    return *(uint32_t*)&h;
}

// ---------------- prep: zero counts + dtype detect + W1/W2 half2 pack -----
__global__ void prep_kernel(const void* ei,
                            const float* __restrict__ W1,
                            const float* __restrict__ W2) {
    int i = blockIdx.x * blockDim.x + threadIdx.x;
    if (i < NN) { g_counts[i] = 0; g_fill[i] = 0; }
    if (i < H1DIM * 64) {
        int n = i >> 6, j = i & 63;
        g_w1h[i] = pack_h2(W1[(2 * j) * H1DIM + n], W1[(2 * j + 1) * H1DIM + n]);
    } else if (i < H1DIM * 64 + CLS * 64) {
        int q = i - H1DIM * 64;
        int n = q >> 6, j = q & 63;
        g_w2h[q] = pack_h2(W2[(2 * j) * CLS + n], W2[(2 * j + 1) * CLS + n]);
    }
    if (blockIdx.x == 0 && threadIdx.x < 32) {
        const long long* e = (const long long*)ei;
        int lane = threadIdx.x;
        int bad = 0;
        for (int j = lane; j < 1024; j += 32) {
            long long v = e[j];
            if (v < 0 || v >= NN) bad = 1;
        }
        unsigned m = __ballot_sync(0xffffffffu, bad);
        if (lane == 0) g_is64 = (m == 0);
    }
}

// ---------------- hist directly from edge_index ----------------
__global__ void hist_kernel(const void* ei) {
    int i = blockIdx.x * blockDim.x + threadIdx.x;
    if (i >= ETOT) return;
    int d;
    if (i >= EE)          d = i - EE;
    else if (g_is64)      d = (int)((const long long*)ei)[EE + i];
    else                  d = ((const int*)ei)[EE + i];
    atomicAdd(&g_counts[d], 1);
}

// ---------------- single-block whole-array scan (1024 thr x 49 items) -----
__global__ void scan_kernel() {
    __shared__ int wsum[32];
    const int tid = threadIdx.x, lane = tid & 31, wid = tid >> 5;
    const int IPT = (NN + 1023) / 1024;   // 49
    const int base = tid * IPT;

    int s = 0;
    for (int j = 0; j < IPT; j++) {
        int idx = base + j;
        if (idx < NN) s += g_counts[idx];
    }
    int xs = s;
#pragma unroll
    for (int off = 1; off < 32; off <<= 1) {
        int y = __shfl_up_sync(0xffffffffu, xs, off);
        if (lane >= off) xs += y;
    }
    if (lane == 31) wsum[wid] = xs;
    __syncthreads();
    if (wid == 0) {
        int ws = wsum[lane];
#pragma unroll
        for (int off = 1; off < 32; off <<= 1) {
            int y = __shfl_up_sync(0xffffffffu, ws, off);
            if (lane >= off) ws += y;
        }
        wsum[lane] = ws;
    }
    __syncthreads();
    int run = xs - s + ((wid > 0) ? wsum[wid - 1] : 0);   // exclusive offset
    for (int j = 0; j < IPT; j++) {
        int idx = base + j;
        if (idx < NN) {
            run += g_counts[idx];
            g_rowptr[idx + 1] = run;
        }
    }
    if (tid == 0) g_rowptr[0] = 0;
}

__global__ void scatter_kernel(const void* ei) {
    int i = blockIdx.x * blockDim.x + threadIdx.x;
    if (i >= ETOT) return;
    int s, d;
    if (i >= EE) {
        s = d = i - EE;
    } else if (g_is64) {
        const long long* e = (const long long*)ei;
        s = (int)e[i]; d = (int)e[EE + i];
    } else {
        const int* e = (const int*)ei;
        s = e[i]; d = e[EE + i];
    }
    int pos = g_rowptr[d] + atomicAdd(&g_fill[d], 1);
    g_srcs[pos] = s;
}

// ---------------- GEMM1 fp16 tensor cores, N-split, full-K resident -------
__global__ void __launch_bounds__(256, 3) gemm1_tc_kernel(
        const float* __restrict__ x,
        const float* __restrict__ as1, const float* __restrict__ ad1) {
    extern __shared__ uint32_t sm[];
    uint32_t* Ws = sm;                     // [n*68 + j], 64 n-rows
    uint32_t* Xs = sm + 64 * WPAD;         // [row*68 + j], 128 rows
    float* sa = (float*)(sm + 64 * WPAD + 128 * WPAD);   // 64
    float* sd = sa + 64;

    const int tid = threadIdx.x;
    const int wid = tid >> 5, lane = tid & 31;
    const int g = lane >> 2, tk = lane & 3;
    const int tile = blockIdx.x >> 1;
    const int nh = blockIdx.x & 1;
    const int m0 = tile * G1M;
    const int ncol0 = nh * 64;

    {
        const uint4* wt4 = (const uint4*)(g_w1h + ncol0 * 64);
        for (int i = tid; i < 64 * 16; i += 256) {
            uint4 v = wt4[i];
            int n = i >> 4, j = (i & 15) * 4;
            *(uint4*)&Ws[n * WPAD + j] = v;
        }
    }
    if (tid < 64) { sa[tid] = as1[ncol0 + tid]; sd[tid] = ad1[ncol0 + tid]; }

    for (int i = tid; i < 2048; i += 256) {
        int row = i >> 4, j4 = (i & 15) * 4;
        int gr = m0 + row; if (gr >= NN) gr = NN - 1;
        const float4* xr = (const float4*)&x[(size_t)gr * FIN + j4 * 2];
        float4 lo = xr[0], hi = xr[1];
        uint4 t;
        t.x = pack_h2(lo.x, lo.y); t.y = pack_h2(lo.z, lo.w);
        t.z = pack_h2(hi.x, hi.y); t.w = pack_h2(hi.z, hi.w);
        *(uint4*)&Xs[row * WPAD + j4] = t;
    }
    __syncthreads();

    float acc[8][4];
#pragma unroll
    for (int nt = 0; nt < 8; nt++)
#pragma unroll
        for (int j = 0; j < 4; j++) acc[nt][j] = 0.f;

#pragma unroll
    for (int ks = 0; ks < 8; ks++) {
        const int j0 = ks * 8;
        const uint32_t* xa = &Xs[(wid * 16 + g) * WPAD + j0 + tk];
        uint32_t a0 = xa[0];
        uint32_t a1 = xa[8 * WPAD];
        uint32_t a2 = xa[4];
        uint32_t a3 = xa[8 * WPAD + 4];
#pragma unroll
        for (int nt = 0; nt < 8; nt++) {
            const uint32_t* wb = &Ws[(nt * 8 + g) * WPAD + j0 + tk];
            uint32_t b0 = wb[0];
            uint32_t b1 = wb[4];
            asm volatile(
                "mma.sync.aligned.m16n8k16.row.col.f32.f16.f16.f32 "
                "{%0,%1,%2,%3}, {%4,%5,%6,%7}, {%8,%9}, {%0,%1,%2,%3};"
                : "+f"(acc[nt][0]), "+f"(acc[nt][1]),
                  "+f"(acc[nt][2]), "+f"(acc[nt][3])
                : "r"(a0), "r"(a1), "r"(a2), "r"(a3), "r"(b0), "r"(b1));
        }
    }

    const int row0 = m0 + wid * 16 + g;
    const int row1 = row0 + 8;
#pragma unroll
    for (int nt = 0; nt < 8; nt++) {
        int col = ncol0 + nt * 8 + 2 * tk;
        if (row0 < NN) {
            uint32_t p = pack_h2(acc[nt][0], acc[nt][1]);
            *(uint32_t*)&g_h1h[(size_t)row0 * H1DIM + col] = p;
        }
        if (row1 < NN) {
            uint32_t p = pack_h2(acc[nt][2], acc[nt][3]);
            *(uint32_t*)&g_h1h[(size_t)row1 * H1DIM + col] = p;
        }
    }

#pragma unroll
    for (int hh = 0; hh < 4; hh++) {
        const int h = nh * 4 + hh;
        float es0 = 0.f, ed0 = 0.f, es1 = 0.f, ed1 = 0.f;
#pragma unroll
        for (int q = 0; q < 2; q++) {
            int nt = 2 * hh + q;
            int col = nt * 8 + 2 * tk;
            float av0 = sa[col], av1 = sa[col + 1];
            float dv0 = sd[col], dv1 = sd[col + 1];
            es0 += acc[nt][0] * av0 + acc[nt][1] * av1;
            ed0 += acc[nt][0] * dv0 + acc[nt][1] * dv1;
            es1 += acc[nt][2] * av0 + acc[nt][3] * av1;
            ed1 += acc[nt][2] * dv0 + acc[nt][3] * dv1;
        }
        es0 += __shfl_down_sync(0xffffffffu, es0, 2);
        es0 += __shfl_down_sync(0xffffffffu, es0, 1);
        ed0 += __shfl_down_sync(0xffffffffu, ed0, 2);
        ed0 += __shfl_down_sync(0xffffffffu, ed0, 1);
        es1 += __shfl_down_sync(0xffffffffu, es1, 2);
        es1 += __shfl_down_sync(0xffffffffu, es1, 1);
        ed1 += __shfl_down_sync(0xffffffffu, ed1, 2);
        ed1 += __shfl_down_sync(0xffffffffu, ed1, 1);
        if (tk == 0) {
            if (row0 < NN) { g_e1s[row0 * NHEAD + h] = es0; g_e1d[row0 * NHEAD + h] = ed0; }
            if (row1 < NN) { g_e1s[row1 * NHEAD + h] = es1; g_e1d[row1 * NHEAD + h] = ed1; }
        }
    }
}

// ---------------- layer-1 aggregation: warp per dst, fp16 gather ----------
__global__ void agg1_kernel(const float* __restrict__ b1) {
    int gw = (blockIdx.x * blockDim.x + threadIdx.x) >> 5;
    int lane = threadIdx.x & 31;
    if (gw >= NN) return;
    const int beg = g_rowptr[gw];
    const int end = g_rowptr[gw + 1];

    const int eh = lane & 7;
    const int sub = lane >> 3;
    const int myhead = lane >> 2;
    const float edh = g_e1d[gw * NHEAD + eh];

    float acc0 = 0.f, acc1 = 0.f, acc2 = 0.f, acc3 = 0.f, ssum = 0.f;
    for (int i = beg; i < end; i += 4) {
        int ei = i + sub;
        int s = 0;
        float w = 0.f;
        if (ei < end) {
            s = g_srcs[ei];
            float a = g_e1s[s * NHEAD + eh] + edh;
            a = a > 0.f ? a : NEG * a;
            w = fexp(a);
        }
#pragma unroll
        for (int j = 0; j < 4; j++) {
            float wj = __shfl_sync(0xffffffffu, w, (j << 3) + myhead);
            int   sj = __shfl_sync(0xffffffffu, s, j << 3);
            if (i + j < end) {
                uint2 hraw = *(const uint2*)(g_h1h + (size_t)sj * H1DIM + lane * 4);
                float2 p0 = __half22float2(*(__half2*)&hraw.x);
                float2 p1 = __half22float2(*(__half2*)&hraw.y);
                acc0 = fmaf(wj, p0.x, acc0);
                acc1 = fmaf(wj, p0.y, acc1);
                acc2 = fmaf(wj, p1.x, acc2);
                acc3 = fmaf(wj, p1.y, acc3);
                ssum += wj;
            }
        }
    }

    float inv = 1.f / (ssum + 1e-16f);
    float4 bv = *(const float4*)(b1 + lane * 4);
    float v0 = acc0 * inv + bv.x;
    float v1 = acc1 * inv + bv.y;
    float v2 = acc2 * inv + bv.z;
    float v3 = acc3 * inv + bv.w;
    v0 = v0 > 0.f ? v0 : (fexp(v0) - 1.f);
    v1 = v1 > 0.f ? v1 : (fexp(v1) - 1.f);
    v2 = v2 > 0.f ? v2 : (fexp(v2) - 1.f);
    v3 = v3 > 0.f ? v3 : (fexp(v3) - 1.f);
    uint2 o;
    o.x = pack_h2(v0, v1);
    o.y = pack_h2(v2, v3);
    *(uint2*)&g_hacth[(size_t)gw * H1DIM + lane * 4] = o;
}

// ---------------- GEMM2 fp16 tensor cores, full-K resident, fused e2 ------
__global__ void __launch_bounds__(256, 3) gemm2_tc_kernel(
        const float* __restrict__ as2, const float* __restrict__ ad2) {
    __shared__ uint32_t Ws[CLS * WPAD];
    __shared__ uint32_t Xs[G1M * WPAD];
    __shared__ float sas[CLS], sad[CLS];

    const int tid = threadIdx.x;
    const int wid = tid >> 5, lane = tid & 31;
    const int g = lane >> 2, tk = lane & 3;
    const int m0 = blockIdx.x * G1M;

    {
        const uint4* wt4 = (const uint4*)g_w2h;
        for (int i = tid; i < CLS * 16; i += 256) {
            uint4 v = wt4[i];
            int n = i >> 4, j = (i & 15) * 4;
            *(uint4*)&Ws[n * WPAD + j] = v;
        }
    }
    if (tid < CLS) { sas[tid] = as2[tid]; sad[tid] = ad2[tid]; }

    for (int i = tid; i < 2048; i += 256) {
        int row = i >> 4, j4 = (i & 15) * 4;
        int gr = m0 + row; if (gr >= NN) gr = NN - 1;
        uint4 v = *(const uint4*)&g_hacth[(size_t)gr * FIN + j4 * 2];
        *(uint4*)&Xs[row * WPAD + j4] = v;
    }
    __syncthreads();

    float acc[5][4];
#pragma unroll
    for (int nt = 0; nt < 5; nt++)
#pragma unroll
        for (int j = 0; j < 4; j++) acc[nt][j] = 0.f;

#pragma unroll
    for (int ks = 0; ks < 8; ks++) {
        const int j0 = ks * 8;
        const uint32_t* xa = &Xs[(wid * 16 + g) * WPAD + j0 + tk];
        uint32_t a0 = xa[0];
        uint32_t a1 = xa[8 * WPAD];
        uint32_t a2 = xa[4];
        uint32_t a3 = xa[8 * WPAD + 4];
#pragma unroll
        for (int nt = 0; nt < 5; nt++) {
            const uint32_t* wb = &Ws[(nt * 8 + g) * WPAD + j0 + tk];
            uint32_t b0 = wb[0];
            uint32_t b1 = wb[4];
            asm volatile(
                "mma.sync.aligned.m16n8k16.row.col.f32.f16.f16.f32 "
                "{%0,%1,%2,%3}, {%4,%5,%6,%7}, {%8,%9}, {%0,%1,%2,%3};"
                : "+f"(acc[nt][0]), "+f"(acc[nt][1]),
                  "+f"(acc[nt][2]), "+f"(acc[nt][3])
                : "r"(a0), "r"(a1), "r"(a2), "r"(a3), "r"(b0), "r"(b1));
        }
    }

    const int row0 = m0 + wid * 16 + g;
    const int row1 = row0 + 8;
#pragma unroll
    for (int nt = 0; nt < 5; nt++) {
        int col = nt * 8 + 2 * tk;
        if (row0 < NN)
            *(uint32_t*)&g_h2h[(size_t)row0 * CLS + col] =
                pack_h2(acc[nt][0], acc[nt][1]);
        if (row1 < NN)
            *(uint32_t*)&g_h2h[(size_t)row1 * CLS + col] =
                pack_h2(acc[nt][2], acc[nt][3]);
    }

    float es0 = 0.f, ed0 = 0.f, es1 = 0.f, ed1 = 0.f;
#pragma unroll
    for (int nt = 0; nt < 5; nt++) {
        int col = nt * 8 + 2 * tk;
        float av0 = sas[col], av1 = sas[col + 1];
        float dv0 = sad[col], dv1 = sad[col + 1];
        es0 += acc[nt][0] * av0 + acc[nt][1] * av1;
        ed0 += acc[nt][0] * dv0 + acc[nt][1] * dv1;
        es1 += acc[nt][2] * av0 + acc[nt][3] * av1;
        ed1 += acc[nt][2] * dv0 + acc[nt][3] * dv1;
    }
    es0 += __shfl_down_sync(0xffffffffu, es0, 2);
    es0 += __shfl_down_sync(0xffffffffu, es0, 1);
    ed0 += __shfl_down_sync(0xffffffffu, ed0, 2);
    ed0 += __shfl_down_sync(0xffffffffu, ed0, 1);
    es1 += __shfl_down_sync(0xffffffffu, es1, 2);
    es1 += __shfl_down_sync(0xffffffffu, es1, 1);
    ed1 += __shfl_down_sync(0xffffffffu, ed1, 2);
    ed1 += __shfl_down_sync(0xffffffffu, ed1, 1);
    if (tk == 0) {
        if (row0 < NN) { g_e2s[row0] = es0; g_e2d[row0] = ed0; }
        if (row1 < NN) { g_e2s[row1] = es1; g_e2d[row1] = ed1; }
    }
}

// ---------------- layer-2 aggregation: warp per dst, fp16 gather ----------
__global__ void agg2_kernel(const float* __restrict__ b2, float* __restrict__ out) {
    int gw = (blockIdx.x * blockDim.x + threadIdx.x) >> 5;
    int lane = threadIdx.x & 31;
    if (gw >= NN) return;
    const int beg = g_rowptr[gw];
    const int end = g_rowptr[gw + 1];
    const float edn = g_e2d[gw];
    const int sub = lane & 3;

    float acc0 = 0.f, acc1 = 0.f, ss = 0.f;
    for (int i = beg; i < end; i += 4) {
        int ei = i + sub;
        int s = 0;
        float w = 0.f;
        if (ei < end) {
            s = g_srcs[ei];
            float a = g_e2s[s] + edn;
            a = a > 0.f ? a : NEG * a;
            w = fexp(a);
        }
#pragma unroll
        for (int j = 0; j < 4; j++) {
            float wj = __shfl_sync(0xffffffffu, w, j);
            int   sj = __shfl_sync(0xffffffffu, s, j);
            if (i + j < end) {
                if (lane < 20) {
                    uint32_t hraw = *(const uint32_t*)(g_h2h + (size_t)sj * CLS + 2 * lane);
                    float2 p = __half22float2(*(__half2*)&hraw);
                    acc0 = fmaf(wj, p.x, acc0);
                    acc1 = fmaf(wj, p.y, acc1);
                }
                ss += wj;
            }
        }
    }
    float inv = 1.f / (ss + 1e-16f);
    if (lane < 20) {
        out[(size_t)gw * CLS + 2 * lane]     = acc0 * inv + __ldg(&b2[2 * lane]);
        out[(size_t)gw * CLS + 2 * lane + 1] = acc1 * inv + __ldg(&b2[2 * lane + 1]);
    }
}

// ---------------- launch ----------------
extern "C" void kernel_launch(void* const* d_in, const int* in_sizes, int n_in,
                              void* d_out, int out_size) {
    const float* x   = (const float*)d_in[0];
    const void*  ei  = d_in[1];
    const float* W1  = (const float*)d_in[2];
    const float* as1 = (const float*)d_in[3];
    const float* ad1 = (const float*)d_in[4];
    const float* b1  = (const float*)d_in[5];
    const float* W2  = (const float*)d_in[6];
    const float* as2 = (const float*)d_in[7];
    const float* ad2 = (const float*)d_in[8];
    const float* b2  = (const float*)d_in[9];
    float* out = (float*)d_out;

    static cudaStream_t s2 = nullptr;
    static cudaEvent_t evFork = nullptr, evJoin = nullptr;
    if (s2 == nullptr) {
        cudaFuncSetAttribute(gemm1_tc_kernel,
                             cudaFuncAttributeMaxDynamicSharedMemorySize, 53248);
        cudaStreamCreateWithFlags(&s2, cudaStreamNonBlocking);
        cudaEventCreateWithFlags(&evFork, cudaEventDisableTiming);
        cudaEventCreateWithFlags(&evJoin, cudaEventDisableTiming);
    }

    // submission order keeps gemm1_tc as the 4th kernel (ncu capture target)
    prep_kernel<<<(NN + 255) / 256, 256>>>(ei, W1, W2);         // 1 (main)
    cudaEventRecord(evFork, 0);
    cudaStreamWaitEvent(s2, evFork, 0);
    hist_kernel<<<(ETOT + 255) / 256, 256, 0, s2>>>(ei);        // 2 (aux)
    scan_kernel<<<1, 1024, 0, s2>>>();                          // 3 (aux)
    gemm1_tc_kernel<<<2 * ((NN + G1M - 1) / G1M), 256, 53248>>>(x, as1, ad1);  // 4
    scatter_kernel<<<(ETOT + 255) / 256, 256, 0, s2>>>(ei);     // 5 (aux)
    cudaEventRecord(evJoin, s2);

    cudaStreamWaitEvent(0, evJoin, 0);
    agg1_kernel<<<(NN + 7) / 8, 256>>>(b1);                     // 6
    gemm2_tc_kernel<<<(NN + G1M - 1) / G1M, 256>>>(as2, ad2);   // 7
    agg2_kernel<<<(NN + 7) / 8, 256>>>(b2, out);                // 8
}

// round 16
// speedup vs baseline: 1.4729x; 1.4729x over previous
#include <cuda_runtime.h>
#include <cuda_fp16.h>
#include <cstdint>

#define NN    50000
#define EE    800000
#define ETOT  (EE + NN)
#define FIN   128
#define H1DIM 128   // HEADS*HID
#define NHEAD 8
#define CLS   40
#define NEG   0.2f
#define G1M   128   // rows per gemm block
#define NBLK  49    // scan blocks
#define WPAD  68    // smem word stride (68 mod 32 == 4 -> conflict-free frags)

// ---------------- device scratch (static, allocation-free) ----------------
__device__ __half   g_h1h[(size_t)NN * H1DIM];    // layer-1 messages, fp16
__device__ __half   g_hacth[(size_t)NN * H1DIM];  // ELU output, fp16
__device__ __half   g_h2h[(size_t)NN * CLS];      // layer-2 messages, fp16
__device__ float    g_e1s[NN * NHEAD];
__device__ float    g_e1d[NN * NHEAD];
__device__ float    g_e2s[NN];
__device__ float    g_e2d[NN];
__device__ int      g_rowptr[NN + 1];
__device__ int      g_counts[NN];
__device__ int      g_fill[NN];
__device__ int      g_srcs[ETOT];
__device__ int      g_bsum[64];
__device__ uint32_t g_w1h[H1DIM * 64];   // W1 half2-packed, n-major: [n*64 + k/2]
__device__ uint32_t g_w2h[CLS * 64];     // W2 half2-packed, n-major
__device__ int      g_is64;

// ---------------- fast exp: pure FFMA/ALU, no MUFU ----------------
__device__ __forceinline__ float fexp(float x) {
    float t = x * 1.442695041f;
    t = fminf(fmaxf(t, -125.f), 125.f);
    float biased = t + 12582912.f;
    int   ni = __float_as_int(biased) - 0x4B400000;
    float n  = biased - 12582912.f;
    float f  = fmaf(-n, 0.69314718056f, x);
    float p  = fmaf(f, 8.3333333e-3f, 4.1666667e-2f);
    p = fmaf(p, f, 0.16666667f);
    p = fmaf(p, f, 0.5f);
    p = fmaf(p, f, 1.0f);
    p = fmaf(p, f, 1.0f);
    return p * __int_as_float((ni + 127) << 23);
}

__device__ __forceinline__ uint32_t pack_h2(float a, float b) {
    __half2 h = __floats2half2_rn(a, b);
    return *(uint32_t*)&h;
}

// ---------------- prep: zero counts + dtype detect + W1/W2 half2 pack -----
__global__ void prep_kernel(const void* ei,
                            const float* __restrict__ W1,
                            const float* __restrict__ W2) {
    int i = blockIdx.x * blockDim.x + threadIdx.x;
    if (i < NN) { g_counts[i] = 0; g_fill[i] = 0; }
    if (i < H1DIM * 64) {
        int n = i >> 6, j = i & 63;
        g_w1h[i] = pack_h2(W1[(2 * j) * H1DIM + n], W1[(2 * j + 1) * H1DIM + n]);
    } else if (i < H1DIM * 64 + CLS * 64) {
        int q = i - H1DIM * 64;
        int n = q >> 6, j = q & 63;
        g_w2h[q] = pack_h2(W2[(2 * j) * CLS + n], W2[(2 * j + 1) * CLS + n]);
    }
    if (blockIdx.x == 0 && threadIdx.x < 32) {
        const long long* e = (const long long*)ei;
        int lane = threadIdx.x;
        int bad = 0;
        for (int j = lane; j < 1024; j += 32) {
            long long v = e[j];
            if (v < 0 || v >= NN) bad = 1;
        }
        unsigned m = __ballot_sync(0xffffffffu, bad);
        if (lane == 0) g_is64 = (m == 0);
    }
}

// ---------------- hist directly from edge_index ----------------
__global__ void hist_kernel(const void* ei) {
    int i = blockIdx.x * blockDim.x + threadIdx.x;
    if (i >= ETOT) return;
    int d;
    if (i >= EE)          d = i - EE;
    else if (g_is64)      d = (int)((const long long*)ei)[EE + i];
    else                  d = ((const int*)ei)[EE + i];
    atomicAdd(&g_counts[d], 1);
}

// ---------------- hierarchical scan (two full-grid kernels) ----------------
__global__ void scan1_kernel() {
    __shared__ int warp_sums[32];
    int tid = threadIdx.x, lane = tid & 31, wid = tid >> 5;
    int idx = blockIdx.x * 1024 + tid;
    int v = (idx < NN) ? g_counts[idx] : 0;
    int xs = v;
#pragma unroll
    for (int off = 1; off < 32; off <<= 1) {
        int y = __shfl_up_sync(0xffffffffu, xs, off);
        if (lane >= off) xs += y;
    }
    if (lane == 31) warp_sums[wid] = xs;
    __syncthreads();
    if (wid == 0) {
        int ws = warp_sums[lane];
#pragma unroll
        for (int off = 1; off < 32; off <<= 1) {
            int y = __shfl_up_sync(0xffffffffu, ws, off);
            if (lane >= off) ws += y;
        }
        warp_sums[lane] = ws;
    }
    __syncthreads();
    int incl = xs + ((wid > 0) ? warp_sums[wid - 1] : 0);
    if (idx < NN) g_rowptr[idx + 1] = incl;
    if (tid == 1023) g_bsum[blockIdx.x] = incl;
}

__global__ void scan23_kernel() {
    __shared__ int soff;
    int tid = threadIdx.x;
    if (tid < 32) {
        int b = blockIdx.x;
        int c = 0;
        if (tid < b)      c += g_bsum[tid];
        if (tid + 32 < b) c += g_bsum[tid + 32];
#pragma unroll
        for (int off = 16; off > 0; off >>= 1)
            c += __shfl_down_sync(0xffffffffu, c, off);
        if (tid == 0) soff = c;
    }
    __syncthreads();
    int idx = blockIdx.x * 1024 + tid;
    if (idx < NN) g_rowptr[idx + 1] += soff;
    if (idx == 0) g_rowptr[0] = 0;
}

__global__ void scatter_kernel(const void* ei) {
    int i = blockIdx.x * blockDim.x + threadIdx.x;
    if (i >= ETOT) return;
    int s, d;
    if (i >= EE) {
        s = d = i - EE;
    } else if (g_is64) {
        const long long* e = (const long long*)ei;
        s = (int)e[i]; d = (int)e[EE + i];
    } else {
        const int* e = (const int*)ei;
        s = e[i]; d = e[EE + i];
    }
    int pos = g_rowptr[d] + atomicAdd(&g_fill[d], 1);
    g_srcs[pos] = s;
}

// ---------------- GEMM1 fp16 tensor cores, N-split, full-K resident -------
__global__ void __launch_bounds__(256, 3) gemm1_tc_kernel(
        const float* __restrict__ x,
        const float* __restrict__ as1, const float* __restrict__ ad1) {
    extern __shared__ uint32_t sm[];
    uint32_t* Ws = sm;                     // [n*68 + j], 64 n-rows
    uint32_t* Xs = sm + 64 * WPAD;         // [row*68 + j], 128 rows
    float* sa = (float*)(sm + 64 * WPAD + 128 * WPAD);   // 64
    float* sd = sa + 64;

    const int tid = threadIdx.x;
    const int wid = tid >> 5, lane = tid & 31;
    const int g = lane >> 2, tk = lane & 3;
    const int tile = blockIdx.x >> 1;
    const int nh = blockIdx.x & 1;
    const int m0 = tile * G1M;
    const int ncol0 = nh * 64;

    {
        const uint4* wt4 = (const uint4*)(g_w1h + ncol0 * 64);
        for (int i = tid; i < 64 * 16; i += 256) {
            uint4 v = wt4[i];
            int n = i >> 4, j = (i & 15) * 4;
            *(uint4*)&Ws[n * WPAD + j] = v;
        }
    }
    if (tid < 64) { sa[tid] = as1[ncol0 + tid]; sd[tid] = ad1[ncol0 + tid]; }

    for (int i = tid; i < 2048; i += 256) {
        int row = i >> 4, j4 = (i & 15) * 4;
        int gr = m0 + row; if (gr >= NN) gr = NN - 1;
        const float4* xr = (const float4*)&x[(size_t)gr * FIN + j4 * 2];
        float4 lo = xr[0], hi = xr[1];
        uint4 t;
        t.x = pack_h2(lo.x, lo.y); t.y = pack_h2(lo.z, lo.w);
        t.z = pack_h2(hi.x, hi.y); t.w = pack_h2(hi.z, hi.w);
        *(uint4*)&Xs[row * WPAD + j4] = t;
    }
    __syncthreads();

    float acc[8][4];
#pragma unroll
    for (int nt = 0; nt < 8; nt++)
#pragma unroll
        for (int j = 0; j < 4; j++) acc[nt][j] = 0.f;

#pragma unroll
    for (int ks = 0; ks < 8; ks++) {
        const int j0 = ks * 8;
        const uint32_t* xa = &Xs[(wid * 16 + g) * WPAD + j0 + tk];
        uint32_t a0 = xa[0];
        uint32_t a1 = xa[8 * WPAD];
        uint32_t a2 = xa[4];
        uint32_t a3 = xa[8 * WPAD + 4];
#pragma unroll
        for (int nt = 0; nt < 8; nt++) {
            const uint32_t* wb = &Ws[(nt * 8 + g) * WPAD + j0 + tk];
            uint32_t b0 = wb[0];
            uint32_t b1 = wb[4];
            asm volatile(
                "mma.sync.aligned.m16n8k16.row.col.f32.f16.f16.f32 "
                "{%0,%1,%2,%3}, {%4,%5,%6,%7}, {%8,%9}, {%0,%1,%2,%3};"
                : "+f"(acc[nt][0]), "+f"(acc[nt][1]),
                  "+f"(acc[nt][2]), "+f"(acc[nt][3])
                : "r"(a0), "r"(a1), "r"(a2), "r"(a3), "r"(b0), "r"(b1));
        }
    }

    const int row0 = m0 + wid * 16 + g;
    const int row1 = row0 + 8;
#pragma unroll
    for (int nt = 0; nt < 8; nt++) {
        int col = ncol0 + nt * 8 + 2 * tk;
        if (row0 < NN) {
            uint32_t p = pack_h2(acc[nt][0], acc[nt][1]);
            *(uint32_t*)&g_h1h[(size_t)row0 * H1DIM + col] = p;
        }
        if (row1 < NN) {
            uint32_t p = pack_h2(acc[nt][2], acc[nt][3]);
            *(uint32_t*)&g_h1h[(size_t)row1 * H1DIM + col] = p;
        }
    }

#pragma unroll
    for (int hh = 0; hh < 4; hh++) {
        const int h = nh * 4 + hh;
        float es0 = 0.f, ed0 = 0.f, es1 = 0.f, ed1 = 0.f;
#pragma unroll
        for (int q = 0; q < 2; q++) {
            int nt = 2 * hh + q;
            int col = nt * 8 + 2 * tk;
            float av0 = sa[col], av1 = sa[col + 1];
            float dv0 = sd[col], dv1 = sd[col + 1];
            es0 += acc[nt][0] * av0 + acc[nt][1] * av1;
            ed0 += acc[nt][0] * dv0 + acc[nt][1] * dv1;
            es1 += acc[nt][2] * av0 + acc[nt][3] * av1;
            ed1 += acc[nt][2] * dv0 + acc[nt][3] * dv1;
        }
        es0 += __shfl_down_sync(0xffffffffu, es0, 2);
        es0 += __shfl_down_sync(0xffffffffu, es0, 1);
        ed0 += __shfl_down_sync(0xffffffffu, ed0, 2);
        ed0 += __shfl_down_sync(0xffffffffu, ed0, 1);
        es1 += __shfl_down_sync(0xffffffffu, es1, 2);
        es1 += __shfl_down_sync(0xffffffffu, es1, 1);
        ed1 += __shfl_down_sync(0xffffffffu, ed1, 2);
        ed1 += __shfl_down_sync(0xffffffffu, ed1, 1);
        if (tk == 0) {
            if (row0 < NN) { g_e1s[row0 * NHEAD + h] = es0; g_e1d[row0 * NHEAD + h] = ed0; }
            if (row1 < NN) { g_e1s[row1 * NHEAD + h] = es1; g_e1d[row1 * NHEAD + h] = ed1; }
        }
    }
}

// ---------------- layer-1 aggregation: warp per dst, fp16 gather ----------
__global__ void agg1_kernel(const float* __restrict__ b1) {
    int gw = (blockIdx.x * blockDim.x + threadIdx.x) >> 5;
    int lane = threadIdx.x & 31;
    if (gw >= NN) return;
    const int beg = g_rowptr[gw];
    const int end = g_rowptr[gw + 1];

    const int eh = lane & 7;
    const int sub = lane >> 3;
    const int myhead = lane >> 2;
    const float edh = g_e1d[gw * NHEAD + eh];

    float acc0 = 0.f, acc1 = 0.f, acc2 = 0.f, acc3 = 0.f, ssum = 0.f;
    for (int i = beg; i < end; i += 4) {
        int ei = i + sub;
        int s = 0;
        float w = 0.f;
        if (ei < end) {
            s = g_srcs[ei];
            float a = g_e1s[s * NHEAD + eh] + edh;
            a = a > 0.f ? a : NEG * a;
            w = fexp(a);
        }
#pragma unroll
        for (int j = 0; j < 4; j++) {
            float wj = __shfl_sync(0xffffffffu, w, (j << 3) + myhead);
            int   sj = __shfl_sync(0xffffffffu, s, j << 3);
            if (i + j < end) {
                uint2 hraw = *(const uint2*)(g_h1h + (size_t)sj * H1DIM + lane * 4);
                float2 p0 = __half22float2(*(__half2*)&hraw.x);
                float2 p1 = __half22float2(*(__half2*)&hraw.y);
                acc0 = fmaf(wj, p0.x, acc0);
                acc1 = fmaf(wj, p0.y, acc1);
                acc2 = fmaf(wj, p1.x, acc2);
                acc3 = fmaf(wj, p1.y, acc3);
                ssum += wj;
            }
        }
    }

    float inv = 1.f / (ssum + 1e-16f);
    float4 bv = *(const float4*)(b1 + lane * 4);
    float v0 = acc0 * inv + bv.x;
    float v1 = acc1 * inv + bv.y;
    float v2 = acc2 * inv + bv.z;
    float v3 = acc3 * inv + bv.w;
    v0 = v0 > 0.f ? v0 : (fexp(v0) - 1.f);
    v1 = v1 > 0.f ? v1 : (fexp(v1) - 1.f);
    v2 = v2 > 0.f ? v2 : (fexp(v2) - 1.f);
    v3 = v3 > 0.f ? v3 : (fexp(v3) - 1.f);
    uint2 o;
    o.x = pack_h2(v0, v1);
    o.y = pack_h2(v2, v3);
    *(uint2*)&g_hacth[(size_t)gw * H1DIM + lane * 4] = o;
}

// ---------------- GEMM2 fp16 tensor cores, full-K resident, fused e2 ------
__global__ void __launch_bounds__(256, 3) gemm2_tc_kernel(
        const float* __restrict__ as2, const float* __restrict__ ad2) {
    __shared__ uint32_t Ws[CLS * WPAD];
    __shared__ uint32_t Xs[G1M * WPAD];
    __shared__ float sas[CLS], sad[CLS];

    const int tid = threadIdx.x;
    const int wid = tid >> 5, lane = tid & 31;
    const int g = lane >> 2, tk = lane & 3;
    const int m0 = blockIdx.x * G1M;

    {
        const uint4* wt4 = (const uint4*)g_w2h;
        for (int i = tid; i < CLS * 16; i += 256) {
            uint4 v = wt4[i];
            int n = i >> 4, j = (i & 15) * 4;
            *(uint4*)&Ws[n * WPAD + j] = v;
        }
    }
    if (tid < CLS) { sas[tid] = as2[tid]; sad[tid] = ad2[tid]; }

    for (int i = tid; i < 2048; i += 256) {
        int row = i >> 4, j4 = (i & 15) * 4;
        int gr = m0 + row; if (gr >= NN) gr = NN - 1;
        uint4 v = *(const uint4*)&g_hacth[(size_t)gr * FIN + j4 * 2];
        *(uint4*)&Xs[row * WPAD + j4] = v;
    }
    __syncthreads();

    float acc[5][4];
#pragma unroll
    for (int nt = 0; nt < 5; nt++)
#pragma unroll
        for (int j = 0; j < 4; j++) acc[nt][j] = 0.f;

#pragma unroll
    for (int ks = 0; ks < 8; ks++) {
        const int j0 = ks * 8;
        const uint32_t* xa = &Xs[(wid * 16 + g) * WPAD + j0 + tk];
        uint32_t a0 = xa[0];
        uint32_t a1 = xa[8 * WPAD];
        uint32_t a2 = xa[4];
        uint32_t a3 = xa[8 * WPAD + 4];
#pragma unroll
        for (int nt = 0; nt < 5; nt++) {
            const uint32_t* wb = &Ws[(nt * 8 + g) * WPAD + j0 + tk];
            uint32_t b0 = wb[0];
            uint32_t b1 = wb[4];
            asm volatile(
                "mma.sync.aligned.m16n8k16.row.col.f32.f16.f16.f32 "
                "{%0,%1,%2,%3}, {%4,%5,%6,%7}, {%8,%9}, {%0,%1,%2,%3};"
                : "+f"(acc[nt][0]), "+f"(acc[nt][1]),
                  "+f"(acc[nt][2]), "+f"(acc[nt][3])
                : "r"(a0), "r"(a1), "r"(a2), "r"(a3), "r"(b0), "r"(b1));
        }
    }

    const int row0 = m0 + wid * 16 + g;
    const int row1 = row0 + 8;
#pragma unroll
    for (int nt = 0; nt < 5; nt++) {
        int col = nt * 8 + 2 * tk;
        if (row0 < NN)
            *(uint32_t*)&g_h2h[(size_t)row0 * CLS + col] =
                pack_h2(acc[nt][0], acc[nt][1]);
        if (row1 < NN)
            *(uint32_t*)&g_h2h[(size_t)row1 * CLS + col] =
                pack_h2(acc[nt][2], acc[nt][3]);
    }

    float es0 = 0.f, ed0 = 0.f, es1 = 0.f, ed1 = 0.f;
#pragma unroll
    for (int nt = 0; nt < 5; nt++) {
        int col = nt * 8 + 2 * tk;
        float av0 = sas[col], av1 = sas[col + 1];
        float dv0 = sad[col], dv1 = sad[col + 1];
        es0 += acc[nt][0] * av0 + acc[nt][1] * av1;
        ed0 += acc[nt][0] * dv0 + acc[nt][1] * dv1;
        es1 += acc[nt][2] * av0 + acc[nt][3] * av1;
        ed1 += acc[nt][2] * dv0 + acc[nt][3] * dv1;
    }
    es0 += __shfl_down_sync(0xffffffffu, es0, 2);
    es0 += __shfl_down_sync(0xffffffffu, es0, 1);
    ed0 += __shfl_down_sync(0xffffffffu, ed0, 2);
    ed0 += __shfl_down_sync(0xffffffffu, ed0, 1);
    es1 += __shfl_down_sync(0xffffffffu, es1, 2);
    es1 += __shfl_down_sync(0xffffffffu, es1, 1);
    ed1 += __shfl_down_sync(0xffffffffu, ed1, 2);
    ed1 += __shfl_down_sync(0xffffffffu, ed1, 1);
    if (tk == 0) {
        if (row0 < NN) { g_e2s[row0] = es0; g_e2d[row0] = ed0; }
        if (row1 < NN) { g_e2s[row1] = es1; g_e2d[row1] = ed1; }
    }
}

// ---------------- layer-2 aggregation: warp per dst, fp16 gather ----------
__global__ void agg2_kernel(const float* __restrict__ b2, float* __restrict__ out) {
    int gw = (blockIdx.x * blockDim.x + threadIdx.x) >> 5;
    int lane = threadIdx.x & 31;
    if (gw >= NN) return;
    const int beg = g_rowptr[gw];
    const int end = g_rowptr[gw + 1];
    const float edn = g_e2d[gw];
    const int sub = lane & 3;

    float acc0 = 0.f, acc1 = 0.f, ss = 0.f;
    for (int i = beg; i < end; i += 4) {
        int ei = i + sub;
        int s = 0;
        float w = 0.f;
        if (ei < end) {
            s = g_srcs[ei];
            float a = g_e2s[s] + edn;
            a = a > 0.f ? a : NEG * a;
            w = fexp(a);
        }
#pragma unroll
        for (int j = 0; j < 4; j++) {
            float wj = __shfl_sync(0xffffffffu, w, j);
            int   sj = __shfl_sync(0xffffffffu, s, j);
            if (i + j < end) {
                if (lane < 20) {
                    uint32_t hraw = *(const uint32_t*)(g_h2h + (size_t)sj * CLS + 2 * lane);
                    float2 p = __half22float2(*(__half2*)&hraw);
                    acc0 = fmaf(wj, p.x, acc0);
                    acc1 = fmaf(wj, p.y, acc1);
                }
                ss += wj;
            }
        }
    }
    float inv = 1.f / (ss + 1e-16f);
    if (lane < 20) {
        out[(size_t)gw * CLS + 2 * lane]     = acc0 * inv + __ldg(&b2[2 * lane]);
        out[(size_t)gw * CLS + 2 * lane + 1] = acc1 * inv + __ldg(&b2[2 * lane + 1]);
    }
}

// ---------------- launch ----------------
extern "C" void kernel_launch(void* const* d_in, const int* in_sizes, int n_in,
                              void* d_out, int out_size) {
    const float* x   = (const float*)d_in[0];
    const void*  ei  = d_in[1];
    const float* W1  = (const float*)d_in[2];
    const float* as1 = (const float*)d_in[3];
    const float* ad1 = (const float*)d_in[4];
    const float* b1  = (const float*)d_in[5];
    const float* W2  = (const float*)d_in[6];
    const float* as2 = (const float*)d_in[7];
    const float* ad2 = (const float*)d_in[8];
    const float* b2  = (const float*)d_in[9];
    float* out = (float*)d_out;

    static cudaStream_t s2 = nullptr;
    static cudaEvent_t evFork = nullptr, evJoin = nullptr;
    if (s2 == nullptr) {
        cudaFuncSetAttribute(gemm1_tc_kernel,
                             cudaFuncAttributeMaxDynamicSharedMemorySize, 53248);
        cudaStreamCreateWithFlags(&s2, cudaStreamNonBlocking);
        cudaEventCreateWithFlags(&evFork, cudaEventDisableTiming);
        cudaEventCreateWithFlags(&evJoin, cudaEventDisableTiming);
    }

    // submission order keeps gemm1_tc as the 4th kernel (ncu capture target)
    prep_kernel<<<(NN + 255) / 256, 256>>>(ei, W1, W2);         // 1 (main)
    cudaEventRecord(evFork, 0);
    cudaStreamWaitEvent(s2, evFork, 0);
    hist_kernel<<<(ETOT + 255) / 256, 256, 0, s2>>>(ei);        // 2 (aux)
    scan1_kernel<<<NBLK, 1024, 0, s2>>>();                      // 3 (aux)
    gemm1_tc_kernel<<<2 * ((NN + G1M - 1) / G1M), 256, 53248>>>(x, as1, ad1);  // 4
    scan23_kernel<<<NBLK, 1024, 0, s2>>>();                     // 5 (aux)
    scatter_kernel<<<(ETOT + 255) / 256, 256, 0, s2>>>(ei);     // 6 (aux)
    cudaEventRecord(evJoin, s2);

    cudaStreamWaitEvent(0, evJoin, 0);
    agg1_kernel<<<(NN + 7) / 8, 256>>>(b1);                     // 7
    gemm2_tc_kernel<<<(NN + G1M - 1) / G1M, 256>>>(as2, ad2);   // 8
    agg2_kernel<<<(NN + 7) / 8, 256>>>(b2, out);                // 9
}

// round 17
// speedup vs baseline: 1.5177x; 1.0304x over previous
#include <cuda_runtime.h>
#include <cuda_fp16.h>
#include <cstdint>

#define NN    50000
#define EE    800000
#define ETOT  (EE + NN)
#define FIN   128
#define H1DIM 128   // HEADS*HID
#define NHEAD 8
#define CLS   40
#define NEG   0.2f
#define G1M   128   // rows per gemm block
#define NBLK  49    // scan blocks
#define WPAD  68    // smem word stride (68 mod 32 == 4 -> conflict-free frags)

// ---------------- device scratch (static, allocation-free) ----------------
__device__ __half   g_h1h[(size_t)NN * H1DIM];    // layer-1 messages, fp16
__device__ __half   g_hacth[(size_t)NN * H1DIM];  // ELU output, fp16
__device__ __half   g_h2h[(size_t)NN * CLS];      // layer-2 messages, fp16
__device__ float    g_e1s[NN * NHEAD];
__device__ float    g_e1d[NN * NHEAD];
__device__ float    g_e2s[NN];
__device__ float    g_e2d[NN];
__device__ int      g_rowptr[NN + 1];
__device__ int      g_counts[NN];
__device__ int      g_fill[NN];
__device__ int      g_srcs[ETOT];
__device__ int      g_bsum[64];
__device__ uint32_t g_w1h[H1DIM * 64];   // W1 half2-packed, n-major: [n*64 + k/2]
__device__ uint32_t g_w2h[CLS * 64];     // W2 half2-packed, n-major
__device__ int      g_is64;

// ---------------- PDL intrinsics ----------------
__device__ __forceinline__ void pdl_trigger() {
    asm volatile("griddepcontrol.launch_dependents;");
}
__device__ __forceinline__ void pdl_wait() {
    asm volatile("griddepcontrol.wait;");
}

// ---------------- fast exp: pure FFMA/ALU, no MUFU ----------------
__device__ __forceinline__ float fexp(float x) {
    float t = x * 1.442695041f;
    t = fminf(fmaxf(t, -125.f), 125.f);
    float biased = t + 12582912.f;
    int   ni = __float_as_int(biased) - 0x4B400000;
    float n  = biased - 12582912.f;
    float f  = fmaf(-n, 0.69314718056f, x);
    float p  = fmaf(f, 8.3333333e-3f, 4.1666667e-2f);
    p = fmaf(p, f, 0.16666667f);
    p = fmaf(p, f, 0.5f);
    p = fmaf(p, f, 1.0f);
    p = fmaf(p, f, 1.0f);
    return p * __int_as_float((ni + 127) << 23);
}

__device__ __forceinline__ uint32_t pack_h2(float a, float b) {
    __half2 h = __floats2half2_rn(a, b);
    return *(uint32_t*)&h;
}

// ---------------- prep: zero counts + dtype detect + W1/W2 half2 pack -----
__global__ void prep_kernel(const void* ei,
                            const float* __restrict__ W1,
                            const float* __restrict__ W2) {
    pdl_trigger();   // gemm1 preamble touches only external x
    int i = blockIdx.x * blockDim.x + threadIdx.x;
    if (i < NN) { g_counts[i] = 0; g_fill[i] = 0; }
    if (i < H1DIM * 64) {
        int n = i >> 6, j = i & 63;
        g_w1h[i] = pack_h2(W1[(2 * j) * H1DIM + n], W1[(2 * j + 1) * H1DIM + n]);
    } else if (i < H1DIM * 64 + CLS * 64) {
        int q = i - H1DIM * 64;
        int n = q >> 6, j = q & 63;
        g_w2h[q] = pack_h2(W2[(2 * j) * CLS + n], W2[(2 * j + 1) * CLS + n]);
    }
    if (blockIdx.x == 0 && threadIdx.x < 32) {
        const long long* e = (const long long*)ei;
        int lane = threadIdx.x;
        int bad = 0;
        for (int j = lane; j < 1024; j += 32) {
            long long v = e[j];
            if (v < 0 || v >= NN) bad = 1;
        }
        unsigned m = __ballot_sync(0xffffffffu, bad);
        if (lane == 0) g_is64 = (m == 0);
    }
}

// ---------------- hist directly from edge_index ----------------
__global__ void hist_kernel(const void* ei) {
    int i = blockIdx.x * blockDim.x + threadIdx.x;
    if (i >= ETOT) return;
    int d;
    if (i >= EE)          d = i - EE;
    else if (g_is64)      d = (int)((const long long*)ei)[EE + i];
    else                  d = ((const int*)ei)[EE + i];
    atomicAdd(&g_counts[d], 1);
}

// ---------------- hierarchical scan (two full-grid kernels) ----------------
__global__ void scan1_kernel() {
    __shared__ int warp_sums[32];
    int tid = threadIdx.x, lane = tid & 31, wid = tid >> 5;
    int idx = blockIdx.x * 1024 + tid;
    int v = (idx < NN) ? g_counts[idx] : 0;
    int xs = v;
#pragma unroll
    for (int off = 1; off < 32; off <<= 1) {
        int y = __shfl_up_sync(0xffffffffu, xs, off);
        if (lane >= off) xs += y;
    }
    if (lane == 31) warp_sums[wid] = xs;
    __syncthreads();
    if (wid == 0) {
        int ws = warp_sums[lane];
#pragma unroll
        for (int off = 1; off < 32; off <<= 1) {
            int y = __shfl_up_sync(0xffffffffu, ws, off);
            if (lane >= off) ws += y;
        }
        warp_sums[lane] = ws;
    }
    __syncthreads();
    int incl = xs + ((wid > 0) ? warp_sums[wid - 1] : 0);
    if (idx < NN) g_rowptr[idx + 1] = incl;
    if (tid == 1023) g_bsum[blockIdx.x] = incl;
}

__global__ void scan23_kernel() {
    pdl_trigger();   // scatter preamble reads only external edge_index
    __shared__ int soff;
    int tid = threadIdx.x;
    if (tid < 32) {
        int b = blockIdx.x;
        int c = 0;
        if (tid < b)      c += g_bsum[tid];
        if (tid + 32 < b) c += g_bsum[tid + 32];
#pragma unroll
        for (int off = 16; off > 0; off >>= 1)
            c += __shfl_down_sync(0xffffffffu, c, off);
        if (tid == 0) soff = c;
    }
    __syncthreads();
    int idx = blockIdx.x * 1024 + tid;
    if (idx < NN) g_rowptr[idx + 1] += soff;
    if (idx == 0) g_rowptr[0] = 0;
}

__global__ void scatter_kernel(const void* ei) {
    int i = blockIdx.x * blockDim.x + threadIdx.x;
    // preamble: bulk edge read from external input (overlaps scan23)
    int s = 0, d = 0;
    if (i < ETOT) {
        if (i >= EE) {
            s = d = i - EE;
        } else if (g_is64) {
            const long long* e = (const long long*)ei;
            s = (int)e[i]; d = (int)e[EE + i];
        } else {
            const int* e = (const int*)ei;
            s = e[i]; d = e[EE + i];
        }
    }
    pdl_wait();      // rowptr ready
    if (i >= ETOT) return;
    int pos = g_rowptr[d] + atomicAdd(&g_fill[d], 1);
    g_srcs[pos] = s;
}

// ---------------- GEMM1 fp16 tensor cores, N-split, full-K resident -------
__global__ void __launch_bounds__(256, 3) gemm1_tc_kernel(
        const float* __restrict__ x,
        const float* __restrict__ as1, const float* __restrict__ ad1) {
    extern __shared__ uint32_t sm[];
    uint32_t* Ws = sm;                     // [n*68 + j], 64 n-rows
    uint32_t* Xs = sm + 64 * WPAD;         // [row*68 + j], 128 rows
    float* sa = (float*)(sm + 64 * WPAD + 128 * WPAD);   // 64
    float* sd = sa + 64;

    const int tid = threadIdx.x;
    const int wid = tid >> 5, lane = tid & 31;
    const int g = lane >> 2, tk = lane & 3;
    const int tile = blockIdx.x >> 1;
    const int nh = blockIdx.x & 1;
    const int m0 = tile * G1M;
    const int ncol0 = nh * 64;

    // preamble: stage X from external input x (independent of prep)
    for (int i = tid; i < 2048; i += 256) {
        int row = i >> 4, j4 = (i & 15) * 4;
        int gr = m0 + row; if (gr >= NN) gr = NN - 1;
        const float4* xr = (const float4*)&x[(size_t)gr * FIN + j4 * 2];
        float4 lo = xr[0], hi = xr[1];
        uint4 t;
        t.x = pack_h2(lo.x, lo.y); t.y = pack_h2(lo.z, lo.w);
        t.z = pack_h2(hi.x, hi.y); t.w = pack_h2(hi.z, hi.w);
        *(uint4*)&Xs[row * WPAD + j4] = t;
    }
    if (tid < 64) { sa[tid] = as1[ncol0 + tid]; sd[tid] = ad1[ncol0 + tid]; }

    pdl_wait();      // g_w1h (prep output) now safe to read
    {
        const uint4* wt4 = (const uint4*)(g_w1h + ncol0 * 64);
        for (int i = tid; i < 64 * 16; i += 256) {
            uint4 v = wt4[i];
            int n = i >> 4, j = (i & 15) * 4;
            *(uint4*)&Ws[n * WPAD + j] = v;
        }
    }
    __syncthreads();

    float acc[8][4];
#pragma unroll
    for (int nt = 0; nt < 8; nt++)
#pragma unroll
        for (int j = 0; j < 4; j++) acc[nt][j] = 0.f;

#pragma unroll
    for (int ks = 0; ks < 8; ks++) {
        const int j0 = ks * 8;
        const uint32_t* xa = &Xs[(wid * 16 + g) * WPAD + j0 + tk];
        uint32_t a0 = xa[0];
        uint32_t a1 = xa[8 * WPAD];
        uint32_t a2 = xa[4];
        uint32_t a3 = xa[8 * WPAD + 4];
#pragma unroll
        for (int nt = 0; nt < 8; nt++) {
            const uint32_t* wb = &Ws[(nt * 8 + g) * WPAD + j0 + tk];
            uint32_t b0 = wb[0];
            uint32_t b1 = wb[4];
            asm volatile(
                "mma.sync.aligned.m16n8k16.row.col.f32.f16.f16.f32 "
                "{%0,%1,%2,%3}, {%4,%5,%6,%7}, {%8,%9}, {%0,%1,%2,%3};"
                : "+f"(acc[nt][0]), "+f"(acc[nt][1]),
                  "+f"(acc[nt][2]), "+f"(acc[nt][3])
                : "r"(a0), "r"(a1), "r"(a2), "r"(a3), "r"(b0), "r"(b1));
        }
    }

    pdl_trigger();   // release agg1 during epilogue

    const int row0 = m0 + wid * 16 + g;
    const int row1 = row0 + 8;
#pragma unroll
    for (int nt = 0; nt < 8; nt++) {
        int col = ncol0 + nt * 8 + 2 * tk;
        if (row0 < NN) {
            uint32_t p = pack_h2(acc[nt][0], acc[nt][1]);
            *(uint32_t*)&g_h1h[(size_t)row0 * H1DIM + col] = p;
        }
        if (row1 < NN) {
            uint32_t p = pack_h2(acc[nt][2], acc[nt][3]);
            *(uint32_t*)&g_h1h[(size_t)row1 * H1DIM + col] = p;
        }
    }

#pragma unroll
    for (int hh = 0; hh < 4; hh++) {
        const int h = nh * 4 + hh;
        float es0 = 0.f, ed0 = 0.f, es1 = 0.f, ed1 = 0.f;
#pragma unroll
        for (int q = 0; q < 2; q++) {
            int nt = 2 * hh + q;
            int col = nt * 8 + 2 * tk;
            float av0 = sa[col], av1 = sa[col + 1];
            float dv0 = sd[col], dv1 = sd[col + 1];
            es0 += acc[nt][0] * av0 + acc[nt][1] * av1;
            ed0 += acc[nt][0] * dv0 + acc[nt][1] * dv1;
            es1 += acc[nt][2] * av0 + acc[nt][3] * av1;
            ed1 += acc[nt][2] * dv0 + acc[nt][3] * dv1;
        }
        es0 += __shfl_down_sync(0xffffffffu, es0, 2);
        es0 += __shfl_down_sync(0xffffffffu, es0, 1);
        ed0 += __shfl_down_sync(0xffffffffu, ed0, 2);
        ed0 += __shfl_down_sync(0xffffffffu, ed0, 1);
        es1 += __shfl_down_sync(0xffffffffu, es1, 2);
        es1 += __shfl_down_sync(0xffffffffu, es1, 1);
        ed1 += __shfl_down_sync(0xffffffffu, ed1, 2);
        ed1 += __shfl_down_sync(0xffffffffu, ed1, 1);
        if (tk == 0) {
            if (row0 < NN) { g_e1s[row0 * NHEAD + h] = es0; g_e1d[row0 * NHEAD + h] = ed0; }
            if (row1 < NN) { g_e1s[row1 * NHEAD + h] = es1; g_e1d[row1 * NHEAD + h] = ed1; }
        }
    }
}

// ---------------- layer-1 aggregation: warp per dst, fp16 gather ----------
__global__ void agg1_kernel(const float* __restrict__ b1) {
    int gw = (blockIdx.x * blockDim.x + threadIdx.x) >> 5;
    int lane = threadIdx.x & 31;
    // preamble: CSR bounds (aux-chain outputs; launch-ordering guarantees done)
    int beg = 0, end = 0;
    if (gw < NN) { beg = g_rowptr[gw]; end = g_rowptr[gw + 1]; }
    float4 bv = (gw < NN) ? *(const float4*)(b1 + lane * 4)
                          : make_float4(0.f, 0.f, 0.f, 0.f);

    pdl_wait();      // gemm1 outputs (h1h, e1s, e1d) now visible
    if (gw >= NN) return;

    const int eh = lane & 7;
    const int sub = lane >> 3;
    const int myhead = lane >> 2;
    const float edh = g_e1d[gw * NHEAD + eh];

    float acc0 = 0.f, acc1 = 0.f, acc2 = 0.f, acc3 = 0.f, ssum = 0.f;
    for (int i = beg; i < end; i += 4) {
        int ei = i + sub;
        int s = 0;
        float w = 0.f;
        if (ei < end) {
            s = g_srcs[ei];
            float a = g_e1s[s * NHEAD + eh] + edh;
            a = a > 0.f ? a : NEG * a;
            w = fexp(a);
        }
#pragma unroll
        for (int j = 0; j < 4; j++) {
            float wj = __shfl_sync(0xffffffffu, w, (j << 3) + myhead);
            int   sj = __shfl_sync(0xffffffffu, s, j << 3);
            if (i + j < end) {
                uint2 hraw = *(const uint2*)(g_h1h + (size_t)sj * H1DIM + lane * 4);
                float2 p0 = __half22float2(*(__half2*)&hraw.x);
                float2 p1 = __half22float2(*(__half2*)&hraw.y);
                acc0 = fmaf(wj, p0.x, acc0);
                acc1 = fmaf(wj, p0.y, acc1);
                acc2 = fmaf(wj, p1.x, acc2);
                acc3 = fmaf(wj, p1.y, acc3);
                ssum += wj;
            }
        }
    }

    pdl_trigger();   // release gemm2 during epilogue

    float inv = 1.f / (ssum + 1e-16f);
    float v0 = acc0 * inv + bv.x;
    float v1 = acc1 * inv + bv.y;
    float v2 = acc2 * inv + bv.z;
    float v3 = acc3 * inv + bv.w;
    v0 = v0 > 0.f ? v0 : (fexp(v0) - 1.f);
    v1 = v1 > 0.f ? v1 : (fexp(v1) - 1.f);
    v2 = v2 > 0.f ? v2 : (fexp(v2) - 1.f);
    v3 = v3 > 0.f ? v3 : (fexp(v3) - 1.f);
    uint2 o;
    o.x = pack_h2(v0, v1);
    o.y = pack_h2(v2, v3);
    *(uint2*)&g_hacth[(size_t)gw * H1DIM + lane * 4] = o;
}

// ---------------- GEMM2 fp16 tensor cores, full-K resident, fused e2 ------
__global__ void __launch_bounds__(256, 3) gemm2_tc_kernel(
        const float* __restrict__ as2, const float* __restrict__ ad2) {
    __shared__ uint32_t Ws[CLS * WPAD];
    __shared__ uint32_t Xs[G1M * WPAD];
    __shared__ float sas[CLS], sad[CLS];

    const int tid = threadIdx.x;
    const int wid = tid >> 5, lane = tid & 31;
    const int g = lane >> 2, tk = lane & 3;
    const int m0 = blockIdx.x * G1M;

    // preamble: external attention vectors only
    if (tid < CLS) { sas[tid] = as2[tid]; sad[tid] = ad2[tid]; }

    pdl_wait();      // agg1 complete (hact ready; transitively prep's w2h too)
    {
        const uint4* wt4 = (const uint4*)g_w2h;
        for (int i = tid; i < CLS * 16; i += 256) {
            uint4 v = wt4[i];
            int n = i >> 4, j = (i & 15) * 4;
            *(uint4*)&Ws[n * WPAD + j] = v;
        }
    }
    for (int i = tid; i < 2048; i += 256) {
        int row = i >> 4, j4 = (i & 15) * 4;
        int gr = m0 + row; if (gr >= NN) gr = NN - 1;
        uint4 v = *(const uint4*)&g_hacth[(size_t)gr * FIN + j4 * 2];
        *(uint4*)&Xs[row * WPAD + j4] = v;
    }
    __syncthreads();

    float acc[5][4];
#pragma unroll
    for (int nt = 0; nt < 5; nt++)
#pragma unroll
        for (int j = 0; j < 4; j++) acc[nt][j] = 0.f;

#pragma unroll
    for (int ks = 0; ks < 8; ks++) {
        const int j0 = ks * 8;
        const uint32_t* xa = &Xs[(wid * 16 + g) * WPAD + j0 + tk];
        uint32_t a0 = xa[0];
        uint32_t a1 = xa[8 * WPAD];
        uint32_t a2 = xa[4];
        uint32_t a3 = xa[8 * WPAD + 4];
#pragma unroll
        for (int nt = 0; nt < 5; nt++) {
            const uint32_t* wb = &Ws[(nt * 8 + g) * WPAD + j0 + tk];
            uint32_t b0 = wb[0];
            uint32_t b1 = wb[4];
            asm volatile(
                "mma.sync.aligned.m16n8k16.row.col.f32.f16.f16.f32 "
                "{%0,%1,%2,%3}, {%4,%5,%6,%7}, {%8,%9}, {%0,%1,%2,%3};"
                : "+f"(acc[nt][0]), "+f"(acc[nt][1]),
                  "+f"(acc[nt][2]), "+f"(acc[nt][3])
                : "r"(a0), "r"(a1), "r"(a2), "r"(a3), "r"(b0), "r"(b1));
        }
    }

    pdl_trigger();   // release agg2 during epilogue

    const int row0 = m0 + wid * 16 + g;
    const int row1 = row0 + 8;
#pragma unroll
    for (int nt = 0; nt < 5; nt++) {
        int col = nt * 8 + 2 * tk;
        if (row0 < NN)
            *(uint32_t*)&g_h2h[(size_t)row0 * CLS + col] =
                pack_h2(acc[nt][0], acc[nt][1]);
        if (row1 < NN)
            *(uint32_t*)&g_h2h[(size_t)row1 * CLS + col] =
                pack_h2(acc[nt][2], acc[nt][3]);
    }

    float es0 = 0.f, ed0 = 0.f, es1 = 0.f, ed1 = 0.f;
#pragma unroll
    for (int nt = 0; nt < 5; nt++) {
        int col = nt * 8 + 2 * tk;
        float av0 = sas[col], av1 = sas[col + 1];
        float dv0 = sad[col], dv1 = sad[col + 1];
        es0 += acc[nt][0] * av0 + acc[nt][1] * av1;
        ed0 += acc[nt][0] * dv0 + acc[nt][1] * dv1;
        es1 += acc[nt][2] * av0 + acc[nt][3] * av1;
        ed1 += acc[nt][2] * dv0 + acc[nt][3] * dv1;
    }
    es0 += __shfl_down_sync(0xffffffffu, es0, 2);
    es0 += __shfl_down_sync(0xffffffffu, es0, 1);
    ed0 += __shfl_down_sync(0xffffffffu, ed0, 2);
    ed0 += __shfl_down_sync(0xffffffffu, ed0, 1);
    es1 += __shfl_down_sync(0xffffffffu, es1, 2);
    es1 += __shfl_down_sync(0xffffffffu, es1, 1);
    ed1 += __shfl_down_sync(0xffffffffu, ed1, 2);
    ed1 += __shfl_down_sync(0xffffffffu, ed1, 1);
    if (tk == 0) {
        if (row0 < NN) { g_e2s[row0] = es0; g_e2d[row0] = ed0; }
        if (row1 < NN) { g_e2s[row1] = es1; g_e2d[row1] = ed1; }
    }
}

// ---------------- layer-2 aggregation: warp per dst, fp16 gather ----------
__global__ void agg2_kernel(const float* __restrict__ b2, float* __restrict__ out) {
    int gw = (blockIdx.x * blockDim.x + threadIdx.x) >> 5;
    int lane = threadIdx.x & 31;
    // preamble: CSR bounds + bias (independent of gemm2)
    int beg = 0, end = 0;
    if (gw < NN) { beg = g_rowptr[gw]; end = g_rowptr[gw + 1]; }
    float b2a = 0.f, b2b = 0.f;
    if (lane < 20) { b2a = __ldg(&b2[2 * lane]); b2b = __ldg(&b2[2 * lane + 1]); }

    pdl_wait();      // gemm2 outputs (h2h, e2s, e2d) now visible
    if (gw >= NN) return;
    const float edn = g_e2d[gw];
    const int sub = lane & 3;

    float acc0 = 0.f, acc1 = 0.f, ss = 0.f;
    for (int i = beg; i < end; i += 4) {
        int ei = i + sub;
        int s = 0;
        float w = 0.f;
        if (ei < end) {
            s = g_srcs[ei];
            float a = g_e2s[s] + edn;
            a = a > 0.f ? a : NEG * a;
            w = fexp(a);
        }
#pragma unroll
        for (int j = 0; j < 4; j++) {
            float wj = __shfl_sync(0xffffffffu, w, j);
            int   sj = __shfl_sync(0xffffffffu, s, j);
            if (i + j < end) {
                if (lane < 20) {
                    uint32_t hraw = *(const uint32_t*)(g_h2h + (size_t)sj * CLS + 2 * lane);
                    float2 p = __half22float2(*(__half2*)&hraw);
                    acc0 = fmaf(wj, p.x, acc0);
                    acc1 = fmaf(wj, p.y, acc1);
                }
                ss += wj;
            }
        }
    }
    float inv = 1.f / (ss + 1e-16f);
    if (lane < 20) {
        out[(size_t)gw * CLS + 2 * lane]     = acc0 * inv + b2a;
        out[(size_t)gw * CLS + 2 * lane + 1] = acc1 * inv + b2b;
    }
}

// ---------------- launch ----------------
template <typename... Args>
static void launch_pdl(void (*kern)(Args...), dim3 grid, dim3 block,
                       size_t smem, cudaStream_t st, Args... args) {
    cudaLaunchConfig_t cfg = {};
    cfg.gridDim = grid;
    cfg.blockDim = block;
    cfg.dynamicSmemBytes = smem;
    cfg.stream = st;
    cudaLaunchAttribute attr[1];
    attr[0].id = cudaLaunchAttributeProgrammaticStreamSerialization;
    attr[0].val.programmaticStreamSerializationAllowed = 1;
    cfg.attrs = attr;
    cfg.numAttrs = 1;
    cudaLaunchKernelEx(&cfg, kern, args...);
}

extern "C" void kernel_launch(void* const* d_in, const int* in_sizes, int n_in,
                              void* d_out, int out_size) {
    const float* x   = (const float*)d_in[0];
    const void*  ei  = d_in[1];
    const float* W1  = (const float*)d_in[2];
    const float* as1 = (const float*)d_in[3];
    const float* ad1 = (const float*)d_in[4];
    const float* b1  = (const float*)d_in[5];
    const float* W2  = (const float*)d_in[6];
    const float* as2 = (const float*)d_in[7];
    const float* ad2 = (const float*)d_in[8];
    const float* b2  = (const float*)d_in[9];
    float* out = (float*)d_out;

    static cudaStream_t s2 = nullptr;
    static cudaEvent_t evFork = nullptr, evJoin = nullptr;
    if (s2 == nullptr) {
        cudaFuncSetAttribute(gemm1_tc_kernel,
                             cudaFuncAttributeMaxDynamicSharedMemorySize, 53248);
        cudaStreamCreateWithFlags(&s2, cudaStreamNonBlocking);
        cudaEventCreateWithFlags(&evFork, cudaEventDisableTiming);
        cudaEventCreateWithFlags(&evJoin, cudaEventDisableTiming);
    }

    // submission order keeps gemm1_tc as the 4th kernel (ncu capture target)
    prep_kernel<<<(NN + 255) / 256, 256>>>(ei, W1, W2);              // 1 (main)
    cudaEventRecord(evFork, 0);
    cudaStreamWaitEvent(s2, evFork, 0);
    hist_kernel<<<(ETOT + 255) / 256, 256, 0, s2>>>(ei);             // 2 (aux)
    scan1_kernel<<<NBLK, 1024, 0, s2>>>();                           // 3 (aux)
    launch_pdl(gemm1_tc_kernel, dim3(2 * ((NN + G1M - 1) / G1M)),
               dim3(256), (size_t)53248, (cudaStream_t)0,
               x, as1, ad1);                                         // 4 (main, PDL on prep)
    scan23_kernel<<<NBLK, 1024, 0, s2>>>();                          // 5 (aux)
    launch_pdl(scatter_kernel, dim3((ETOT + 255) / 256),
               dim3(256), (size_t)0, s2, ei);                        // 6 (aux, PDL on scan23)
    cudaEventRecord(evJoin, s2);

    cudaStreamWaitEvent(0, evJoin, 0);
    launch_pdl(agg1_kernel, dim3((NN + 7) / 8), dim3(256),
               (size_t)0, (cudaStream_t)0, b1);                      // 7 (PDL on gemm1)
    launch_pdl(gemm2_tc_kernel, dim3((NN + G1M - 1) / G1M), dim3(256),
               (size_t)0, (cudaStream_t)0, as2, ad2);                // 8 (PDL on agg1)
    launch_pdl(agg2_kernel, dim3((NN + 7) / 8), dim3(256),
               (size_t)0, (cudaStream_t)0, b2, out);                 // 9 (PDL on gemm2)
}